// round 14
// baseline (speedup 1.0000x reference)
#include <cuda_runtime.h>
#include <cuda_fp16.h>
#include <cstdint>

#define WS    8
#define MQ    4
#define HEADS 8
#define DIM   256
#define HD    32
#define BATCH 4
#define IMGH  128
#define IMGW  128
#define NWIN  256
#define BW    (BATCH*NWIN)   // 1024 windows
#define WS2   64
#define NQ    (MQ*WS2)       // 256
#define ROWS_Q  (BW*NQ)      // 262144
#define ROWS_KV (BW*WS2)     // 65536

__device__ __half g_q   [ROWS_Q  * DIM];
__device__ __half g_kv  [ROWS_KV * 2 * DIM];
__device__ __half g_att [ROWS_Q  * DIM];
__device__ __half g_bias[HEADS * WS2 * WS2];     // [h][q][k] fp16
// transposed fp16 weights, [n][k] k-contiguous: wq [0,256) wkv [256,768) wp [768,1024)
__device__ __half g_wt  [1024 * DIM];

__device__ __forceinline__ uint32_t pkh2(float a, float b) {
    __half2 h = __floats2half2_rn(a, b);
    return *(uint32_t*)&h;
}
__device__ __forceinline__ void mma_f16(float c[4],
    uint32_t a0, uint32_t a1, uint32_t a2, uint32_t a3,
    uint32_t b0, uint32_t b1)
{
    asm volatile(
        "mma.sync.aligned.m16n8k16.row.col.f32.f16.f16.f32 "
        "{%0,%1,%2,%3}, {%4,%5,%6,%7}, {%8,%9}, {%0,%1,%2,%3};"
        : "+f"(c[0]), "+f"(c[1]), "+f"(c[2]), "+f"(c[3])
        : "r"(a0), "r"(a1), "r"(a2), "r"(a3), "r"(b0), "r"(b1));
}
__device__ __forceinline__ void ldsm_x4(uint32_t& r0, uint32_t& r1,
                                        uint32_t& r2, uint32_t& r3, uint32_t addr)
{
    asm volatile("ldmatrix.sync.aligned.m8n8.x4.shared.b16 {%0,%1,%2,%3}, [%4];"
                 : "=r"(r0), "=r"(r1), "=r"(r2), "=r"(r3) : "r"(addr));
}
#define CP_ASYNC16(dst, src) \
    asm volatile("cp.async.ca.shared.global [%0], [%1], 16;" :: "r"(dst), "l"(src) : "memory")
#define CP_COMMIT()  asm volatile("cp.async.commit_group;" ::: "memory")
#define CP_WAIT0()   asm volatile("cp.async.wait_group 0;" ::: "memory")

// swizzled byte offset within a [rows][32]-half sub-tile (64B rows, 4 x 16B chunks)
__device__ __forceinline__ uint32_t sw_off(int row, int kc) {
    return (uint32_t)(row * 64 + ((kc ^ ((row >> 1) & 3)) << 4));
}

// ---------------------------------------------------------------------------
// prep kernels
// ---------------------------------------------------------------------------
__global__ void bias_prep_kernel(const float* __restrict__ btab)
{
    const int h = blockIdx.x;
    const int t = threadIdx.x;
    #pragma unroll
    for (int i = 0; i < 16; i++) {
        int e  = t + i * 256;
        int qp = e >> 6, kp = e & 63;
        int dr = (qp >> 3) - (kp >> 3) + 7;
        int dc = (qp & 7)  - (kp & 7)  + 7;
        g_bias[h * 4096 + e] = __float2half(btab[(dr * 15 + dc) * HEADS + h]);
    }
}
__global__ void w_prep_kernel(const float* __restrict__ Wq,
                              const float* __restrict__ Wkv,
                              const float* __restrict__ Wp)
{
    const int idx = blockIdx.x * 256 + threadIdx.x;
    const int row = idx >> 8;
    const int k   = idx & 255;
    float v;
    if (row < 256)       v = Wq [(size_t)k * 256 + row];
    else if (row < 768)  v = Wkv[(size_t)k * 512 + (row - 256)];
    else                 v = Wp [(size_t)k * 256 + (row - 768)];
    g_wt[idx] = __float2half(v);
}

// ---------------------------------------------------------------------------
// fp16 GEMM (fp32 accum): C[M,N] = A[M,256] @ W[256,N] + bias[N]
// Block 128x128, BK=64 (4 iters), 8 warps (4x2), warp tile 32x64.
// Stage = two 32-half sub-tiles of the verified swizzled layout.
// W staged via cp.async (no regs); A via register prefetch (+fp16 pack).
// ---------------------------------------------------------------------------
template<bool GATHER, bool AHALF, bool CHALF>
__global__ __launch_bounds__(256, 2) void gemm_f16_kernel(
    const void* __restrict__ Av, const __half* __restrict__ Wt,
    const float* __restrict__ bias, void* __restrict__ Cv, int N)
{
    __shared__ __half Asm[2][2][128 * 32];   // [stage][sub][row*32]
    __shared__ __half Wsm[2][2][128 * 32];

    const int t    = threadIdx.x;
    const int bm   = blockIdx.y, bn = blockIdx.x;
    const int lane = t & 31, warp = t >> 5;
    const int wm   = warp >> 1;
    const int wnn  = warp & 1;
    const int g    = lane >> 2;
    const int tq   = lane & 3;
    const int l15  = lane & 15, lhi = lane >> 4;

    // A stager: row = t>>1, sub = t&1 (k-halves [sub*32, sub*32+32) of BK=64)
    const int arow = t >> 1, asub = t & 1;
    size_t aoff;
    if (GATHER) {
        const int r    = bm * 128 + arow;
        const int wwin = r >> 6, p = r & 63;
        const int b    = wwin >> 8, widx = wwin & 255;
        const int wy   = widx >> 4, wx = widx & 15;
        const int py   = wy * 8 + (p >> 3);
        const int px   = wx * 8 + (p & 7);
        aoff = (((size_t)b * IMGH + py) * IMGW + px) * DIM;
    } else {
        aoff = (size_t)(bm * 128 + arow) * DIM;
    }
    const float*  ArowF = (const float*)Av + aoff + asub * 32;
    const __half* ArowH = (const __half*)Av + aoff + asub * 32;

    // W stager: row wn_ = t>>1, sub wsub = t&1
    const int wn_ = t >> 1, wsub = t & 1;
    const __half* WrowB = Wt + (size_t)(bn * 128 + wn_) * DIM + wsub * 32;

    const uint32_t aBase = (uint32_t)__cvta_generic_to_shared(Asm);
    const uint32_t wBase = (uint32_t)__cvta_generic_to_shared(Wsm);
    const uint32_t aStRow = aBase + (uint32_t)asub * 8192 + (uint32_t)arow * 64;
    const int      aStSw  = (arow >> 1) & 3;
    const uint32_t wStRow = wBase + (uint32_t)wsub * 8192 + (uint32_t)wn_ * 64;
    const int      wStSw  = (wn_ >> 1) & 3;

    // ldsm lane addresses (within a sub-tile)
    uint32_t aRowOff[2]; int aS[2];
    #pragma unroll
    for (int mi = 0; mi < 2; mi++) {
        int row = wm * 32 + mi * 16 + l15;
        aRowOff[mi] = (uint32_t)row * 64;
        aS[mi]      = (row >> 1) & 3;
    }
    uint32_t bRowOff[4]; int bS[4];
    #pragma unroll
    for (int nt = 0; nt < 4; nt++) {
        int row = wnn * 64 + nt * 16 + l15;
        bRowOff[nt] = (uint32_t)row * 64;
        bS[nt]      = (row >> 1) & 3;
    }

    float acc[2][8][4];
    #pragma unroll
    for (int mi = 0; mi < 2; mi++)
        #pragma unroll
        for (int ni = 0; ni < 8; ni++)
            #pragma unroll
            for (int j = 0; j < 4; j++) acc[mi][ni][j] = 0.f;

    uint32_t apk[16];

    // ---- A global load for iteration it (32 halves) into apk ----
    auto loadA = [&](int it) {
        const int k0 = it * 64;
        if (AHALF) {
            const uint4* ap = (const uint4*)(ArowH + k0);
            uint4 u0 = ap[0], u1 = ap[1], u2 = ap[2], u3 = ap[3];
            apk[0]=u0.x; apk[1]=u0.y; apk[2]=u0.z; apk[3]=u0.w;
            apk[4]=u1.x; apk[5]=u1.y; apk[6]=u1.z; apk[7]=u1.w;
            apk[8]=u2.x; apk[9]=u2.y; apk[10]=u2.z; apk[11]=u2.w;
            apk[12]=u3.x; apk[13]=u3.y; apk[14]=u3.z; apk[15]=u3.w;
        } else {
            const float* ap = ArowF + k0;
            #pragma unroll
            for (int j = 0; j < 8; j++) {
                float4 v = *(const float4*)(ap + j * 4);
                apk[2*j]   = pkh2(v.x, v.y);
                apk[2*j+1] = pkh2(v.z, v.w);
            }
        }
    };
    auto storeA = [&](int stage) {
        char* base = (char*)0;
        uint32_t dst0 = aStRow + (uint32_t)stage * 16384;
        (void)base;
        #pragma unroll
        for (int q = 0; q < 4; q++) {
            uint32_t dst = dst0 + (uint32_t)(((q ^ aStSw) << 4));
            asm volatile("st.shared.v4.b32 [%0], {%1,%2,%3,%4};"
                         :: "r"(dst), "r"(apk[4*q]), "r"(apk[4*q+1]),
                            "r"(apk[4*q+2]), "r"(apk[4*q+3]) : "memory");
        }
    };
    auto issueW = [&](int it, int stage) {
        const __half* src = WrowB + it * 64;
        uint32_t dst0 = wStRow + (uint32_t)stage * 16384;
        #pragma unroll
        for (int q = 0; q < 4; q++) {
            uint32_t dst = dst0 + (uint32_t)(((q ^ wStSw) << 4));
            CP_ASYNC16(dst, src + q * 8);
        }
    };

    // ---- prologue: stage 0 ----
    issueW(0, 0);
    CP_COMMIT();
    loadA(0);
    storeA(0);
    CP_WAIT0();
    __syncthreads();

    for (int it = 0; it < 4; it++) {
        const uint32_t stageOff = (uint32_t)(it & 1) * 16384;

        // issue next stage loads
        if (it < 3) {
            issueW(it + 1, (it + 1) & 1);
            CP_COMMIT();
            loadA(it + 1);
        }

        // compute 4 k16 blocks (2 sub-tiles x 2)
        #pragma unroll
        for (int kb = 0; kb < 4; kb++) {
            const uint32_t subOff = stageOff + (uint32_t)(kb >> 1) * 8192;
            const int kc = 2 * (kb & 1) + lhi;
            uint32_t a[2][4];
            #pragma unroll
            for (int mi = 0; mi < 2; mi++)
                ldsm_x4(a[mi][0], a[mi][1], a[mi][2], a[mi][3],
                        aBase + subOff + aRowOff[mi] + (uint32_t)(((kc ^ aS[mi]) << 4)));
            uint32_t b[4][4];
            #pragma unroll
            for (int nt = 0; nt < 4; nt++)
                ldsm_x4(b[nt][0], b[nt][1], b[nt][2], b[nt][3],
                        wBase + subOff + bRowOff[nt] + (uint32_t)(((kc ^ bS[nt]) << 4)));
            #pragma unroll
            for (int mi = 0; mi < 2; mi++)
                #pragma unroll
                for (int nt = 0; nt < 4; nt++) {
                    mma_f16(acc[mi][2*nt],   a[mi][0], a[mi][1], a[mi][2], a[mi][3],
                            b[nt][0], b[nt][2]);
                    mma_f16(acc[mi][2*nt+1], a[mi][0], a[mi][1], a[mi][2], a[mi][3],
                            b[nt][1], b[nt][3]);
                }
        }

        if (it < 3) {
            storeA((it + 1) & 1);
            CP_WAIT0();
        }
        __syncthreads();
    }

    // ---- epilogue ----
    #pragma unroll
    for (int mi = 0; mi < 2; mi++) {
        const int r0 = bm * 128 + wm * 32 + mi * 16 + g;
        #pragma unroll
        for (int ni = 0; ni < 8; ni++) {
            const int col = bn * 128 + wnn * 64 + ni * 8 + 2 * tq;
            float2 bv = *(const float2*)(bias + col);
            float c0 = acc[mi][ni][0] + bv.x, c1 = acc[mi][ni][1] + bv.y;
            float c2 = acc[mi][ni][2] + bv.x, c3 = acc[mi][ni][3] + bv.y;
            if (CHALF) {
                __half* C = (__half*)Cv;
                *(uint32_t*)(C + (size_t)r0 * N + col)       = pkh2(c0, c1);
                *(uint32_t*)(C + (size_t)(r0 + 8) * N + col) = pkh2(c2, c3);
            } else {
                float* C = (float*)Cv;
                *(float2*)(C + (size_t)r0 * N + col)       = make_float2(c0, c1);
                *(float2*)(C + (size_t)(r0 + 8) * N + col) = make_float2(c2, c3);
            }
        }
    }
}

// ---------------------------------------------------------------------------
// fp16 tensor-core attention, register-resident P (unchanged from R13).
// ---------------------------------------------------------------------------
__global__ __launch_bounds__(256) void attn_mma_kernel()
{
    __shared__ uint2  Qs2[256][12];
    __shared__ uint2  Kt2[64][12];
    __shared__ __half Vt_h[32][72];
    __shared__ __half Bs_h[64][66];

    const int blk = blockIdx.x;
    const int win = blk >> 3;
    const int h   = blk & 7;
    const int t   = threadIdx.x;
    const int lane = t & 31, warp = t >> 5;
    const int g   = lane >> 2;
    const int tq  = lane & 3;
    const int slot = (tq + ((g & 3) + 2 * (g >> 2))) & 3;

    {
        const __half* qp = g_q + ((size_t)(win * NQ + t)) * DIM + h * HD;
        const int rot = ((t & 3) + 2 * ((t >> 2) & 1)) & 3;
        const uint4* qp4 = (const uint4*)qp;
        uint4 u0 = qp4[0], u1 = qp4[1], u2 = qp4[2], u3 = qp4[3];
        uint32_t w[16] = {u0.x,u0.y,u0.z,u0.w, u1.x,u1.y,u1.z,u1.w,
                          u2.x,u2.y,u2.z,u2.w, u3.x,u3.y,u3.z,u3.w};
        #pragma unroll
        for (int q = 0; q < 4; q++) {
            Qs2[t][((q + rot) & 3)]     = make_uint2(w[q],     w[q + 4]);
            Qs2[t][4 + ((q + rot) & 3)] = make_uint2(w[8 + q], w[12 + q]);
        }
    }
    if (t < 64) {
        const __half* kp = g_kv + (size_t)(win * WS2 + t) * 512 + h * HD;
        const int rot = ((t & 3) + 2 * ((t >> 2) & 1)) & 3;
        const uint4* kp4 = (const uint4*)kp;
        uint4 u0 = kp4[0], u1 = kp4[1], u2 = kp4[2], u3 = kp4[3];
        uint32_t w[16] = {u0.x,u0.y,u0.z,u0.w, u1.x,u1.y,u1.z,u1.w,
                          u2.x,u2.y,u2.z,u2.w, u3.x,u3.y,u3.z,u3.w};
        #pragma unroll
        for (int q = 0; q < 4; q++) {
            Kt2[t][((q + rot) & 3)]     = make_uint2(w[q],     w[q + 4]);
            Kt2[t][4 + ((q + rot) & 3)] = make_uint2(w[8 + q], w[12 + q]);
        }
    } else if (t < 128) {
        const int key = t - 64;
        const __half2* vp2 = (const __half2*)(g_kv + (size_t)(win * WS2 + key) * 512
                                              + DIM + h * HD);
        #pragma unroll
        for (int j = 0; j < 16; j++) {
            __half2 v = vp2[j];
            Vt_h[2 * j][key]     = __low2half(v);
            Vt_h[2 * j + 1][key] = __high2half(v);
        }
    }
    {
        const __half* gb = g_bias + h * 4096;
        #pragma unroll
        for (int i = 0; i < 2; i++) {
            int idx = t + i * 256;
            int qp = idx >> 3, c8 = (idx & 7) * 8;
            uint4 u = *(const uint4*)(gb + qp * 64 + c8);
            uint32_t* dst = (uint32_t*)((char*)&Bs_h[qp][0] + c8 * 2);
            dst[0] = u.x; dst[1] = u.y; dst[2] = u.z; dst[3] = u.w;
        }
    }
    __syncthreads();

    float acc[2][8][4];
    #pragma unroll
    for (int mi = 0; mi < 2; mi++)
        #pragma unroll
        for (int ni = 0; ni < 8; ni++)
            #pragma unroll
            for (int j = 0; j < 4; j++) acc[mi][ni][j] = 0.f;

    #pragma unroll
    for (int kb = 0; kb < 2; kb++) {
        const int c = kb * 4 + slot;
        uint2 lo[2], hi[2];
        #pragma unroll
        for (int mi = 0; mi < 2; mi++) {
            const int r0 = warp * 32 + mi * 16 + g;
            lo[mi] = Qs2[r0][c];
            hi[mi] = Qs2[r0 + 8][c];
        }
        uint2 bf[8];
        #pragma unroll
        for (int ni = 0; ni < 8; ni++)
            bf[ni] = Kt2[ni * 8 + g][c];
        #pragma unroll
        for (int mi = 0; mi < 2; mi++)
            #pragma unroll
            for (int ni = 0; ni < 8; ni++)
                mma_f16(acc[mi][ni], lo[mi].x, hi[mi].x, lo[mi].y, hi[mi].y,
                        bf[ni].x, bf[ni].y);
    }

    const float scale = 0.17677669529663687f;
    float inv_[2][2];
    #pragma unroll
    for (int mi = 0; mi < 2; mi++) {
        const int rA = warp * 32 + mi * 16 + g;
        const int qA = rA & 63, qB = (rA + 8) & 63;
        float mA = -1e30f, mB = -1e30f;
        #pragma unroll
        for (int ni = 0; ni < 8; ni++) {
            const int col = ni * 8 + 2 * tq;
            float2 bA = __half22float2(*(const __half2*)&Bs_h[qA][col]);
            float2 bB = __half22float2(*(const __half2*)&Bs_h[qB][col]);
            acc[mi][ni][0] = acc[mi][ni][0] * scale + bA.x;
            acc[mi][ni][1] = acc[mi][ni][1] * scale + bA.y;
            acc[mi][ni][2] = acc[mi][ni][2] * scale + bB.x;
            acc[mi][ni][3] = acc[mi][ni][3] * scale + bB.y;
            mA = fmaxf(mA, fmaxf(acc[mi][ni][0], acc[mi][ni][1]));
            mB = fmaxf(mB, fmaxf(acc[mi][ni][2], acc[mi][ni][3]));
        }
        mA = fmaxf(mA, __shfl_xor_sync(0xffffffff, mA, 1));
        mA = fmaxf(mA, __shfl_xor_sync(0xffffffff, mA, 2));
        mB = fmaxf(mB, __shfl_xor_sync(0xffffffff, mB, 1));
        mB = fmaxf(mB, __shfl_xor_sync(0xffffffff, mB, 2));
        float sA = 0.f, sB = 0.f;
        #pragma unroll
        for (int ni = 0; ni < 8; ni++) {
            float e0 = __expf(acc[mi][ni][0] - mA);
            float e1 = __expf(acc[mi][ni][1] - mA);
            float e2 = __expf(acc[mi][ni][2] - mB);
            float e3 = __expf(acc[mi][ni][3] - mB);
            acc[mi][ni][0] = e0; acc[mi][ni][1] = e1;
            acc[mi][ni][2] = e2; acc[mi][ni][3] = e3;
            sA += e0 + e1; sB += e2 + e3;
        }
        sA += __shfl_xor_sync(0xffffffff, sA, 1);
        sA += __shfl_xor_sync(0xffffffff, sA, 2);
        sB += __shfl_xor_sync(0xffffffff, sB, 1);
        sB += __shfl_xor_sync(0xffffffff, sB, 2);
        inv_[mi][0] = 1.f / sA;
        inv_[mi][1] = 1.f / sB;
    }

    float o[2][4][4];
    #pragma unroll
    for (int mi = 0; mi < 2; mi++)
        #pragma unroll
        for (int ni = 0; ni < 4; ni++)
            #pragma unroll
            for (int j = 0; j < 4; j++) o[mi][ni][j] = 0.f;

    #pragma unroll
    for (int kb = 0; kb < 4; kb++) {
        uint32_t a0[2], a1[2], a2[2], a3[2];
        #pragma unroll
        for (int mi = 0; mi < 2; mi++) {
            a0[mi] = pkh2(acc[mi][2*kb][0],     acc[mi][2*kb][1]);
            a1[mi] = pkh2(acc[mi][2*kb][2],     acc[mi][2*kb][3]);
            a2[mi] = pkh2(acc[mi][2*kb+1][0],   acc[mi][2*kb+1][1]);
            a3[mi] = pkh2(acc[mi][2*kb+1][2],   acc[mi][2*kb+1][3]);
        }
        #pragma unroll
        for (int ni = 0; ni < 4; ni++) {
            const __half* vrow = &Vt_h[ni * 8 + g][0];
            uint32_t b0 = *(const uint32_t*)(vrow + 16 * kb + 2 * tq);
            uint32_t b1 = *(const uint32_t*)(vrow + 16 * kb + 8 + 2 * tq);
            #pragma unroll
            for (int mi = 0; mi < 2; mi++)
                mma_f16(o[mi][ni], a0[mi], a1[mi], a2[mi], a3[mi], b0, b1);
        }
    }

    #pragma unroll
    for (int mi = 0; mi < 2; mi++) {
        const int r = win * NQ + warp * 32 + mi * 16 + g;
        const float ivA = inv_[mi][0], ivB = inv_[mi][1];
        #pragma unroll
        for (int ni = 0; ni < 4; ni++) {
            const int col = h * HD + ni * 8 + 2 * tq;
            *(uint32_t*)(g_att + (size_t)r * DIM + col) =
                pkh2(o[mi][ni][0] * ivA, o[mi][ni][1] * ivA);
            *(uint32_t*)(g_att + (size_t)(r + 8) * DIM + col) =
                pkh2(o[mi][ni][2] * ivB, o[mi][ni][3] * ivB);
        }
    }
}

// ---------------------------------------------------------------------------
extern "C" void kernel_launch(void* const* d_in, const int* in_sizes, int n_in,
                              void* d_out, int out_size)
{
    const float* gauss = (const float*)d_in[0];
    const float* img   = (const float*)d_in[1];
    const float* btab  = (const float*)d_in[2];
    const float* Wq    = (const float*)d_in[3];
    const float* bq    = (const float*)d_in[4];
    const float* Wkv   = (const float*)d_in[5];
    const float* bkv   = (const float*)d_in[6];
    const float* Wp    = (const float*)d_in[7];
    const float* bp    = (const float*)d_in[8];
    float* out = (float*)d_out;

    void* pq = nullptr;   cudaGetSymbolAddress(&pq, g_q);
    void* pkv = nullptr;  cudaGetSymbolAddress(&pkv, g_kv);
    void* pa = nullptr;   cudaGetSymbolAddress(&pa, g_att);
    void* pwt = nullptr;  cudaGetSymbolAddress(&pwt, g_wt);
    const __half* wt = (const __half*)pwt;

    // 0) prep: bias table + transposed fp16 weights
    bias_prep_kernel<<<HEADS, 256>>>(btab);
    w_prep_kernel<<<1024, 256>>>(Wq, Wkv, Wp);
    // 1) Q projection: fp32 A -> fp16 C
    gemm_f16_kernel<false, false, true>
        <<<dim3(DIM / 128, ROWS_Q / 128), 256>>>(gauss, wt, bq, pq, DIM);
    // 2) KV projection (window gather): fp32 A -> fp16 C
    gemm_f16_kernel<true, false, true>
        <<<dim3((2 * DIM) / 128, ROWS_KV / 128), 256>>>(img, wt + 256 * DIM, bkv, pkv, 2 * DIM);
    // 3) Attention (fp16 MMA, register-resident P, precomputed bias)
    attn_mma_kernel<<<BW * HEADS, 256>>>();
    // 4) Output projection: fp16 A -> fp32 C (d_out)
    gemm_f16_kernel<false, true, false>
        <<<dim3(DIM / 128, ROWS_Q / 128), 256>>>(pa, wt + 768 * DIM, bp, out, DIM);
}

// round 15
// speedup vs baseline: 1.2493x; 1.2493x over previous
#include <cuda_runtime.h>
#include <cuda_fp16.h>
#include <cstdint>

#define WS    8
#define MQ    4
#define HEADS 8
#define DIM   256
#define HD    32
#define BATCH 4
#define IMGH  128
#define IMGW  128
#define NWIN  256
#define BW    (BATCH*NWIN)   // 1024 windows
#define WS2   64
#define NQ    (MQ*WS2)       // 256
#define ROWS_Q  (BW*NQ)      // 262144
#define ROWS_KV (BW*WS2)     // 65536

__device__ __half g_q   [ROWS_Q  * DIM];
__device__ __half g_kv  [ROWS_KV * 2 * DIM];
__device__ __half g_att [ROWS_Q  * DIM];
__device__ __half g_bias[HEADS * WS2 * WS2];     // [h][q][k] fp16
// transposed fp16 weights, [n][k] k-contiguous: wq [0,256) wkv [256,768) wp [768,1024)
__device__ __half g_wt  [1024 * DIM];

__device__ __forceinline__ uint32_t pkh2(float a, float b) {
    __half2 h = __floats2half2_rn(a, b);
    return *(uint32_t*)&h;
}
__device__ __forceinline__ void mma_f16(float c[4],
    uint32_t a0, uint32_t a1, uint32_t a2, uint32_t a3,
    uint32_t b0, uint32_t b1)
{
    asm volatile(
        "mma.sync.aligned.m16n8k16.row.col.f32.f16.f16.f32 "
        "{%0,%1,%2,%3}, {%4,%5,%6,%7}, {%8,%9}, {%0,%1,%2,%3};"
        : "+f"(c[0]), "+f"(c[1]), "+f"(c[2]), "+f"(c[3])
        : "r"(a0), "r"(a1), "r"(a2), "r"(a3), "r"(b0), "r"(b1));
}
__device__ __forceinline__ void ldsm_x4(uint32_t& r0, uint32_t& r1,
                                        uint32_t& r2, uint32_t& r3, uint32_t addr)
{
    asm volatile("ldmatrix.sync.aligned.m8n8.x4.shared.b16 {%0,%1,%2,%3}, [%4];"
                 : "=r"(r0), "=r"(r1), "=r"(r2), "=r"(r3) : "r"(addr));
}
__device__ __forceinline__ void ldsm_x4_t(uint32_t& r0, uint32_t& r1,
                                          uint32_t& r2, uint32_t& r3, uint32_t addr)
{
    asm volatile("ldmatrix.sync.aligned.m8n8.x4.trans.shared.b16 {%0,%1,%2,%3}, [%4];"
                 : "=r"(r0), "=r"(r1), "=r"(r2), "=r"(r3) : "r"(addr));
}

// swizzled byte offset within a [rows][32]-half tile (64B rows, 4 x 16B chunks)
__device__ __forceinline__ uint32_t sw_off(int row, int kc) {
    return (uint32_t)(row * 64 + ((kc ^ ((row >> 1) & 3)) << 4));
}

// ---------------------------------------------------------------------------
// prep kernels
// ---------------------------------------------------------------------------
__global__ void bias_prep_kernel(const float* __restrict__ btab)
{
    const int h = blockIdx.x;
    const int t = threadIdx.x;
    #pragma unroll
    for (int i = 0; i < 16; i++) {
        int e  = t + i * 256;
        int qp = e >> 6, kp = e & 63;
        int dr = (qp >> 3) - (kp >> 3) + 7;
        int dc = (qp & 7)  - (kp & 7)  + 7;
        g_bias[h * 4096 + e] = __float2half(btab[(dr * 15 + dc) * HEADS + h]);
    }
}
__global__ void w_prep_kernel(const float* __restrict__ Wq,
                              const float* __restrict__ Wkv,
                              const float* __restrict__ Wp)
{
    const int idx = blockIdx.x * 256 + threadIdx.x;
    const int row = idx >> 8;
    const int k   = idx & 255;
    float v;
    if (row < 256)       v = Wq [(size_t)k * 256 + row];
    else if (row < 768)  v = Wkv[(size_t)k * 512 + (row - 256)];
    else                 v = Wp [(size_t)k * 256 + (row - 768)];
    g_wt[idx] = __float2half(v);
}

// ---------------------------------------------------------------------------
// fp16 GEMM (fp32 accum) — exact R13 configuration (known-good 662us total).
// Block 128x128, BK=32, 8 warps (4x2), warp tile 32x64, mma.m16n8k16.
// W from pre-transposed fp16 g_wt rows; double-buffered swizzled smem.
// ---------------------------------------------------------------------------
template<bool GATHER, bool AHALF, bool CHALF>
__global__ __launch_bounds__(256, 2) void gemm_f16_kernel(
    const void* __restrict__ Av, const __half* __restrict__ Wt,
    const float* __restrict__ bias, void* __restrict__ Cv, int N)
{
    __shared__ __half Asm[2][128 * 32];
    __shared__ __half Wsm[2][128 * 32];

    const int t    = threadIdx.x;
    const int bm   = blockIdx.y, bn = blockIdx.x;
    const int lane = t & 31, warp = t >> 5;
    const int wm   = warp >> 1;
    const int wnn  = warp & 1;
    const int g    = lane >> 2;
    const int tq   = lane & 3;
    const int l15  = lane & 15, lhi = lane >> 4;

    const int arow = t >> 1, as_ = t & 1;
    size_t aoff;
    if (GATHER) {
        const int r    = bm * 128 + arow;
        const int wwin = r >> 6, p = r & 63;
        const int b    = wwin >> 8, widx = wwin & 255;
        const int wy   = widx >> 4, wx = widx & 15;
        const int py   = wy * 8 + (p >> 3);
        const int px   = wx * 8 + (p & 7);
        aoff = (((size_t)b * IMGH + py) * IMGW + px) * DIM;
    } else {
        aoff = (size_t)(bm * 128 + arow) * DIM;
    }
    const float*  ArowF = (const float*)Av + aoff;
    const __half* ArowH = (const __half*)Av + aoff;
    const uint32_t aSt0 = sw_off(arow, 2 * as_);
    const uint32_t aSt1 = sw_off(arow, 2 * as_ + 1);

    const int wn_ = t >> 1, kbw = t & 1;
    const __half* Wrow = Wt + (size_t)(bn * 128 + wn_) * DIM + kbw * 16;
    const uint32_t wSt0 = sw_off(wn_, 2 * kbw);
    const uint32_t wSt1 = sw_off(wn_, 2 * kbw + 1);

    const uint32_t aBase = (uint32_t)__cvta_generic_to_shared(Asm);
    const uint32_t wBase = (uint32_t)__cvta_generic_to_shared(Wsm);
    uint32_t aRow[2]; int aS[2];
    #pragma unroll
    for (int mi = 0; mi < 2; mi++) {
        int row = wm * 32 + mi * 16 + l15;
        aRow[mi] = aBase + row * 64;
        aS[mi]   = (row >> 1) & 3;
    }
    uint32_t bRow[4]; int bS[4];
    #pragma unroll
    for (int nt = 0; nt < 4; nt++) {
        int row = wnn * 64 + nt * 16 + l15;
        bRow[nt] = wBase + row * 64;
        bS[nt]   = (row >> 1) & 3;
    }

    float acc[2][8][4];
    #pragma unroll
    for (int mi = 0; mi < 2; mi++)
        #pragma unroll
        for (int ni = 0; ni < 8; ni++)
            #pragma unroll
            for (int j = 0; j < 4; j++) acc[mi][ni][j] = 0.f;

    uint32_t apk[8], wpk[8];

    {
        if (AHALF) {
            const uint4* ap = (const uint4*)(ArowH + as_ * 16);
            uint4 u0 = ap[0], u1 = ap[1];
            apk[0]=u0.x; apk[1]=u0.y; apk[2]=u0.z; apk[3]=u0.w;
            apk[4]=u1.x; apk[5]=u1.y; apk[6]=u1.z; apk[7]=u1.w;
        } else {
            const float* ap = ArowF + as_ * 16;
            float4 v0 = *(const float4*)(ap);
            float4 v1 = *(const float4*)(ap + 4);
            float4 v2 = *(const float4*)(ap + 8);
            float4 v3 = *(const float4*)(ap + 12);
            apk[0]=pkh2(v0.x,v0.y); apk[1]=pkh2(v0.z,v0.w);
            apk[2]=pkh2(v1.x,v1.y); apk[3]=pkh2(v1.z,v1.w);
            apk[4]=pkh2(v2.x,v2.y); apk[5]=pkh2(v2.z,v2.w);
            apk[6]=pkh2(v3.x,v3.y); apk[7]=pkh2(v3.z,v3.w);
        }
        const uint4* wp4 = (const uint4*)Wrow;
        uint4 w0 = wp4[0], w1 = wp4[1];
        wpk[0]=w0.x; wpk[1]=w0.y; wpk[2]=w0.z; wpk[3]=w0.w;
        wpk[4]=w1.x; wpk[5]=w1.y; wpk[6]=w1.z; wpk[7]=w1.w;

        char* aT = (char*)Asm[0];
        char* wT = (char*)Wsm[0];
        *(uint4*)(aT + aSt0) = make_uint4(apk[0], apk[1], apk[2], apk[3]);
        *(uint4*)(aT + aSt1) = make_uint4(apk[4], apk[5], apk[6], apk[7]);
        *(uint4*)(wT + wSt0) = make_uint4(wpk[0], wpk[1], wpk[2], wpk[3]);
        *(uint4*)(wT + wSt1) = make_uint4(wpk[4], wpk[5], wpk[6], wpk[7]);
    }
    __syncthreads();

    for (int it = 0; it < 8; it++) {
        const uint32_t bufOff = (uint32_t)(it & 1) * 8192;

        if (it < 7) {
            const int k0 = (it + 1) * 32;
            if (AHALF) {
                const uint4* ap = (const uint4*)(ArowH + k0 + as_ * 16);
                uint4 u0 = ap[0], u1 = ap[1];
                apk[0]=u0.x; apk[1]=u0.y; apk[2]=u0.z; apk[3]=u0.w;
                apk[4]=u1.x; apk[5]=u1.y; apk[6]=u1.z; apk[7]=u1.w;
            } else {
                const float* ap = ArowF + k0 + as_ * 16;
                float4 v0 = *(const float4*)(ap);
                float4 v1 = *(const float4*)(ap + 4);
                float4 v2 = *(const float4*)(ap + 8);
                float4 v3 = *(const float4*)(ap + 12);
                apk[0]=pkh2(v0.x,v0.y); apk[1]=pkh2(v0.z,v0.w);
                apk[2]=pkh2(v1.x,v1.y); apk[3]=pkh2(v1.z,v1.w);
                apk[4]=pkh2(v2.x,v2.y); apk[5]=pkh2(v2.z,v2.w);
                apk[6]=pkh2(v3.x,v3.y); apk[7]=pkh2(v3.z,v3.w);
            }
            const uint4* wp4 = (const uint4*)(Wrow + k0);
            uint4 w0 = wp4[0], w1 = wp4[1];
            wpk[0]=w0.x; wpk[1]=w0.y; wpk[2]=w0.z; wpk[3]=w0.w;
            wpk[4]=w1.x; wpk[5]=w1.y; wpk[6]=w1.z; wpk[7]=w1.w;
        }

        #pragma unroll
        for (int kb = 0; kb < 2; kb++) {
            const int kc = 2 * kb + lhi;
            uint32_t a[2][4];
            #pragma unroll
            for (int mi = 0; mi < 2; mi++)
                ldsm_x4(a[mi][0], a[mi][1], a[mi][2], a[mi][3],
                        aRow[mi] + bufOff + (uint32_t)(((kc ^ aS[mi]) << 4)));
            uint32_t b[4][4];
            #pragma unroll
            for (int nt = 0; nt < 4; nt++)
                ldsm_x4(b[nt][0], b[nt][1], b[nt][2], b[nt][3],
                        bRow[nt] + bufOff + (uint32_t)(((kc ^ bS[nt]) << 4)));
            #pragma unroll
            for (int mi = 0; mi < 2; mi++)
                #pragma unroll
                for (int nt = 0; nt < 4; nt++) {
                    mma_f16(acc[mi][2*nt],   a[mi][0], a[mi][1], a[mi][2], a[mi][3],
                            b[nt][0], b[nt][2]);
                    mma_f16(acc[mi][2*nt+1], a[mi][0], a[mi][1], a[mi][2], a[mi][3],
                            b[nt][1], b[nt][3]);
                }
        }

        if (it < 7) {
            char* aT = (char*)Asm[(it + 1) & 1];
            char* wT = (char*)Wsm[(it + 1) & 1];
            *(uint4*)(aT + aSt0) = make_uint4(apk[0], apk[1], apk[2], apk[3]);
            *(uint4*)(aT + aSt1) = make_uint4(apk[4], apk[5], apk[6], apk[7]);
            *(uint4*)(wT + wSt0) = make_uint4(wpk[0], wpk[1], wpk[2], wpk[3]);
            *(uint4*)(wT + wSt1) = make_uint4(wpk[4], wpk[5], wpk[6], wpk[7]);
        }
        __syncthreads();
    }

    #pragma unroll
    for (int mi = 0; mi < 2; mi++) {
        const int r0 = bm * 128 + wm * 32 + mi * 16 + g;
        #pragma unroll
        for (int ni = 0; ni < 8; ni++) {
            const int col = bn * 128 + wnn * 64 + ni * 8 + 2 * tq;
            float2 bv = *(const float2*)(bias + col);
            float c0 = acc[mi][ni][0] + bv.x, c1 = acc[mi][ni][1] + bv.y;
            float c2 = acc[mi][ni][2] + bv.x, c3 = acc[mi][ni][3] + bv.y;
            if (CHALF) {
                __half* C = (__half*)Cv;
                *(uint32_t*)(C + (size_t)r0 * N + col)       = pkh2(c0, c1);
                *(uint32_t*)(C + (size_t)(r0 + 8) * N + col) = pkh2(c2, c3);
            } else {
                float* C = (float*)Cv;
                *(float2*)(C + (size_t)r0 * N + col)       = make_float2(c0, c1);
                *(float2*)(C + (size_t)(r0 + 8) * N + col) = make_float2(c2, c3);
            }
        }
    }
}

// ---------------------------------------------------------------------------
// Attention: row-major padded staging + ldmatrix everywhere.
// Q/K/V staged row-major with 8-half pad (stride 20 words: conflict-free).
// Q A-frags: ldsm.x4; K B-frags: ldsm.x4 (non-trans, [n][k] rows like GEMM);
// V B-frags: ldsm.x4.trans (HW transpose, no scalar scatter staging).
// Accumulator layout / softmax / register-resident P unchanged.
// ---------------------------------------------------------------------------
#define QSTR 40   // halves per Q/K/V row (32 + 8 pad) = 80 bytes
__global__ __launch_bounds__(256) void attn_mma_kernel()
{
    __shared__ __half Qs[256 * QSTR];
    __shared__ __half Ks[64 * QSTR];
    __shared__ __half Vs[64 * QSTR];
    __shared__ __half Bs_h[64][66];

    const int blk = blockIdx.x;
    const int win = blk >> 3;
    const int h   = blk & 7;
    const int t   = threadIdx.x;
    const int lane = t & 31, warp = t >> 5;
    const int g   = lane >> 2;
    const int tq  = lane & 3;
    const int l15 = lane & 15, lhi = lane >> 4;
    const int l7  = lane & 7,  l8  = (lane >> 3) & 1;

    const uint32_t qBase = (uint32_t)__cvta_generic_to_shared(Qs);
    const uint32_t kBase = (uint32_t)__cvta_generic_to_shared(Ks);
    const uint32_t vBase = (uint32_t)__cvta_generic_to_shared(Vs);

    // ---- stage Q: thread t -> row t (4 x STS.128) ----
    {
        const uint4* qp4 = (const uint4*)(g_q + ((size_t)(win * NQ + t)) * DIM + h * HD);
        const uint32_t dst = qBase + (uint32_t)t * 80;
        uint4 u0 = qp4[0], u1 = qp4[1], u2 = qp4[2], u3 = qp4[3];
        asm volatile("st.shared.v4.b32 [%0], {%1,%2,%3,%4};" :: "r"(dst),      "r"(u0.x),"r"(u0.y),"r"(u0.z),"r"(u0.w) : "memory");
        asm volatile("st.shared.v4.b32 [%0], {%1,%2,%3,%4};" :: "r"(dst + 16), "r"(u1.x),"r"(u1.y),"r"(u1.z),"r"(u1.w) : "memory");
        asm volatile("st.shared.v4.b32 [%0], {%1,%2,%3,%4};" :: "r"(dst + 32), "r"(u2.x),"r"(u2.y),"r"(u2.z),"r"(u2.w) : "memory");
        asm volatile("st.shared.v4.b32 [%0], {%1,%2,%3,%4};" :: "r"(dst + 48), "r"(u3.x),"r"(u3.y),"r"(u3.z),"r"(u3.w) : "memory");
    }
    // ---- stage K (threads 0..63) / V (threads 64..127), row-major ----
    if (t < 128) {
        const int key = t & 63;
        const size_t src = (size_t)(win * WS2 + key) * 512 + ((t < 64) ? 0 : (size_t)DIM) + h * HD;
        const uint4* p4 = (const uint4*)(g_kv + src);
        const uint32_t dst = ((t < 64) ? kBase : vBase) + (uint32_t)key * 80;
        uint4 u0 = p4[0], u1 = p4[1], u2 = p4[2], u3 = p4[3];
        asm volatile("st.shared.v4.b32 [%0], {%1,%2,%3,%4};" :: "r"(dst),      "r"(u0.x),"r"(u0.y),"r"(u0.z),"r"(u0.w) : "memory");
        asm volatile("st.shared.v4.b32 [%0], {%1,%2,%3,%4};" :: "r"(dst + 16), "r"(u1.x),"r"(u1.y),"r"(u1.z),"r"(u1.w) : "memory");
        asm volatile("st.shared.v4.b32 [%0], {%1,%2,%3,%4};" :: "r"(dst + 32), "r"(u2.x),"r"(u2.y),"r"(u2.z),"r"(u2.w) : "memory");
        asm volatile("st.shared.v4.b32 [%0], {%1,%2,%3,%4};" :: "r"(dst + 48), "r"(u3.x),"r"(u3.y),"r"(u3.z),"r"(u3.w) : "memory");
    }
    // ---- stage bias (coalesced from precomputed table) ----
    {
        const __half* gb = g_bias + h * 4096;
        #pragma unroll
        for (int i = 0; i < 2; i++) {
            int idx = t + i * 256;
            int qp = idx >> 3, c8 = (idx & 7) * 8;
            uint4 u = *(const uint4*)(gb + qp * 64 + c8);
            uint32_t* dst = (uint32_t*)((char*)&Bs_h[qp][0] + c8 * 2);
            dst[0] = u.x; dst[1] = u.y; dst[2] = u.z; dst[3] = u.w;
        }
    }
    __syncthreads();

    // ---- QK^T: warp tile 32(q) x 64(key), K = 32 (2 k16 blocks) ----
    float acc[2][8][4];
    #pragma unroll
    for (int mi = 0; mi < 2; mi++)
        #pragma unroll
        for (int ni = 0; ni < 8; ni++)
            #pragma unroll
            for (int j = 0; j < 4; j++) acc[mi][ni][j] = 0.f;

    #pragma unroll
    for (int kb = 0; kb < 2; kb++) {
        const uint32_t cOff = (uint32_t)(2 * kb + lhi) * 16;
        uint32_t a[2][4];
        #pragma unroll
        for (int mi = 0; mi < 2; mi++)
            ldsm_x4(a[mi][0], a[mi][1], a[mi][2], a[mi][3],
                    qBase + (uint32_t)(warp * 32 + mi * 16 + l15) * 80 + cOff);
        uint32_t b[4][4];
        #pragma unroll
        for (int ng = 0; ng < 4; ng++)
            ldsm_x4(b[ng][0], b[ng][1], b[ng][2], b[ng][3],
                    kBase + (uint32_t)(ng * 16 + l15) * 80 + cOff);
        #pragma unroll
        for (int mi = 0; mi < 2; mi++)
            #pragma unroll
            for (int ng = 0; ng < 4; ng++) {
                mma_f16(acc[mi][2*ng],   a[mi][0], a[mi][1], a[mi][2], a[mi][3],
                        b[ng][0], b[ng][2]);
                mma_f16(acc[mi][2*ng+1], a[mi][0], a[mi][1], a[mi][2], a[mi][3],
                        b[ng][1], b[ng][3]);
            }
    }

    // ---- scale + bias + softmax (unchanged layout) ----
    const float scale = 0.17677669529663687f;
    float inv_[2][2];
    #pragma unroll
    for (int mi = 0; mi < 2; mi++) {
        const int rA = warp * 32 + mi * 16 + g;
        const int qA = rA & 63, qB = (rA + 8) & 63;
        float mA = -1e30f, mB = -1e30f;
        #pragma unroll
        for (int ni = 0; ni < 8; ni++) {
            const int col = ni * 8 + 2 * tq;
            float2 bA = __half22float2(*(const __half2*)&Bs_h[qA][col]);
            float2 bB = __half22float2(*(const __half2*)&Bs_h[qB][col]);
            acc[mi][ni][0] = acc[mi][ni][0] * scale + bA.x;
            acc[mi][ni][1] = acc[mi][ni][1] * scale + bA.y;
            acc[mi][ni][2] = acc[mi][ni][2] * scale + bB.x;
            acc[mi][ni][3] = acc[mi][ni][3] * scale + bB.y;
            mA = fmaxf(mA, fmaxf(acc[mi][ni][0], acc[mi][ni][1]));
            mB = fmaxf(mB, fmaxf(acc[mi][ni][2], acc[mi][ni][3]));
        }
        mA = fmaxf(mA, __shfl_xor_sync(0xffffffff, mA, 1));
        mA = fmaxf(mA, __shfl_xor_sync(0xffffffff, mA, 2));
        mB = fmaxf(mB, __shfl_xor_sync(0xffffffff, mB, 1));
        mB = fmaxf(mB, __shfl_xor_sync(0xffffffff, mB, 2));
        float sA = 0.f, sB = 0.f;
        #pragma unroll
        for (int ni = 0; ni < 8; ni++) {
            float e0 = __expf(acc[mi][ni][0] - mA);
            float e1 = __expf(acc[mi][ni][1] - mA);
            float e2 = __expf(acc[mi][ni][2] - mB);
            float e3 = __expf(acc[mi][ni][3] - mB);
            acc[mi][ni][0] = e0; acc[mi][ni][1] = e1;
            acc[mi][ni][2] = e2; acc[mi][ni][3] = e3;
            sA += e0 + e1; sB += e2 + e3;
        }
        sA += __shfl_xor_sync(0xffffffff, sA, 1);
        sA += __shfl_xor_sync(0xffffffff, sA, 2);
        sB += __shfl_xor_sync(0xffffffff, sB, 1);
        sB += __shfl_xor_sync(0xffffffff, sB, 2);
        inv_[mi][0] = 1.f / sA;
        inv_[mi][1] = 1.f / sB;
    }

    // ---- PV: P in registers; V B-frags via ldsm.x4.trans ----
    float o[2][4][4];
    #pragma unroll
    for (int mi = 0; mi < 2; mi++)
        #pragma unroll
        for (int ni = 0; ni < 4; ni++)
            #pragma unroll
            for (int j = 0; j < 4; j++) o[mi][ni][j] = 0.f;

    #pragma unroll
    for (int kb = 0; kb < 4; kb++) {
        uint32_t a0[2], a1[2], a2[2], a3[2];
        #pragma unroll
        for (int mi = 0; mi < 2; mi++) {
            a0[mi] = pkh2(acc[mi][2*kb][0],     acc[mi][2*kb][1]);
            a1[mi] = pkh2(acc[mi][2*kb][2],     acc[mi][2*kb][3]);
            a2[mi] = pkh2(acc[mi][2*kb+1][0],   acc[mi][2*kb+1][1]);
            a3[mi] = pkh2(acc[mi][2*kb+1][2],   acc[mi][2*kb+1][3]);
        }
        // key row for this lane within the kb-th 16-key block
        const uint32_t vRow = vBase + (uint32_t)(kb * 16 + l8 * 8 + l7) * 80;
        #pragma unroll
        for (int ndp = 0; ndp < 2; ndp++) {
            // tiles: r0=(key lo8, d chunk 2ndp) r1=(key hi8, same)
            //        r2=(key lo8, chunk 2ndp+1) r3=(key hi8, +1)
            uint32_t b0, b1, b2, b3;
            ldsm_x4_t(b0, b1, b2, b3, vRow + (uint32_t)(ndp * 2 + lhi) * 16);
            #pragma unroll
            for (int mi = 0; mi < 2; mi++) {
                mma_f16(o[mi][2*ndp],   a0[mi], a1[mi], a2[mi], a3[mi], b0, b1);
                mma_f16(o[mi][2*ndp+1], a0[mi], a1[mi], a2[mi], a3[mi], b2, b3);
            }
        }
    }

    // ---- normalize + store O ----
    #pragma unroll
    for (int mi = 0; mi < 2; mi++) {
        const int r = win * NQ + warp * 32 + mi * 16 + g;
        const float ivA = inv_[mi][0], ivB = inv_[mi][1];
        #pragma unroll
        for (int ni = 0; ni < 4; ni++) {
            const int col = h * HD + ni * 8 + 2 * tq;
            *(uint32_t*)(g_att + (size_t)r * DIM + col) =
                pkh2(o[mi][ni][0] * ivA, o[mi][ni][1] * ivA);
            *(uint32_t*)(g_att + (size_t)(r + 8) * DIM + col) =
                pkh2(o[mi][ni][2] * ivB, o[mi][ni][3] * ivB);
        }
    }
}

// ---------------------------------------------------------------------------
extern "C" void kernel_launch(void* const* d_in, const int* in_sizes, int n_in,
                              void* d_out, int out_size)
{
    const float* gauss = (const float*)d_in[0];
    const float* img   = (const float*)d_in[1];
    const float* btab  = (const float*)d_in[2];
    const float* Wq    = (const float*)d_in[3];
    const float* bq    = (const float*)d_in[4];
    const float* Wkv   = (const float*)d_in[5];
    const float* bkv   = (const float*)d_in[6];
    const float* Wp    = (const float*)d_in[7];
    const float* bp    = (const float*)d_in[8];
    float* out = (float*)d_out;

    void* pq = nullptr;   cudaGetSymbolAddress(&pq, g_q);
    void* pkv = nullptr;  cudaGetSymbolAddress(&pkv, g_kv);
    void* pa = nullptr;   cudaGetSymbolAddress(&pa, g_att);
    void* pwt = nullptr;  cudaGetSymbolAddress(&pwt, g_wt);
    const __half* wt = (const __half*)pwt;

    // 0) prep: bias table + transposed fp16 weights
    bias_prep_kernel<<<HEADS, 256>>>(btab);
    w_prep_kernel<<<1024, 256>>>(Wq, Wkv, Wp);
    // 1) Q projection: fp32 A -> fp16 C
    gemm_f16_kernel<false, false, true>
        <<<dim3(DIM / 128, ROWS_Q / 128), 256>>>(gauss, wt, bq, pq, DIM);
    // 2) KV projection (window gather): fp32 A -> fp16 C
    gemm_f16_kernel<true, false, true>
        <<<dim3((2 * DIM) / 128, ROWS_KV / 128), 256>>>(img, wt + 256 * DIM, bkv, pkv, 2 * DIM);
    // 3) Attention (ldmatrix staging, register-resident P)
    attn_mma_kernel<<<BW * HEADS, 256>>>();
    // 4) Output projection: fp16 A -> fp32 C (d_out)
    gemm_f16_kernel<false, true, false>
        <<<dim3(DIM / 128, ROWS_Q / 128), 256>>>(pa, wt + 768 * DIM, bp, out, DIM);
}

// round 16
// speedup vs baseline: 1.2740x; 1.0198x over previous
#include <cuda_runtime.h>
#include <cuda_fp16.h>
#include <cstdint>

#define WS    8
#define MQ    4
#define HEADS 8
#define DIM   256
#define HD    32
#define BATCH 4
#define IMGH  128
#define IMGW  128
#define NWIN  256
#define BW    (BATCH*NWIN)   // 1024 windows
#define WS2   64
#define NQ    (MQ*WS2)       // 256
#define ROWS_Q  (BW*NQ)      // 262144
#define ROWS_KV (BW*WS2)     // 65536

__device__ __half g_q   [ROWS_Q  * DIM];
__device__ __half g_kv  [ROWS_KV * 2 * DIM];
__device__ __half g_att [ROWS_Q  * DIM];
__device__ __half g_bias[HEADS * WS2 * WS2];     // [h][q][k] fp16
// transposed fp16 weights, [n][k] k-contiguous: wq [0,256) wkv [256,768) wp [768,1024)
__device__ __half g_wt  [1024 * DIM];

__device__ __forceinline__ uint32_t pkh2(float a, float b) {
    __half2 h = __floats2half2_rn(a, b);
    return *(uint32_t*)&h;
}
__device__ __forceinline__ void mma_f16(float c[4],
    uint32_t a0, uint32_t a1, uint32_t a2, uint32_t a3,
    uint32_t b0, uint32_t b1)
{
    asm volatile(
        "mma.sync.aligned.m16n8k16.row.col.f32.f16.f16.f32 "
        "{%0,%1,%2,%3}, {%4,%5,%6,%7}, {%8,%9}, {%0,%1,%2,%3};"
        : "+f"(c[0]), "+f"(c[1]), "+f"(c[2]), "+f"(c[3])
        : "r"(a0), "r"(a1), "r"(a2), "r"(a3), "r"(b0), "r"(b1));
}
__device__ __forceinline__ void ldsm_x4(uint32_t& r0, uint32_t& r1,
                                        uint32_t& r2, uint32_t& r3, uint32_t addr)
{
    asm volatile("ldmatrix.sync.aligned.m8n8.x4.shared.b16 {%0,%1,%2,%3}, [%4];"
                 : "=r"(r0), "=r"(r1), "=r"(r2), "=r"(r3) : "r"(addr));
}
__device__ __forceinline__ void ldsm_x4_t(uint32_t& r0, uint32_t& r1,
                                          uint32_t& r2, uint32_t& r3, uint32_t addr)
{
    asm volatile("ldmatrix.sync.aligned.m8n8.x4.trans.shared.b16 {%0,%1,%2,%3}, [%4];"
                 : "=r"(r0), "=r"(r1), "=r"(r2), "=r"(r3) : "r"(addr));
}
#define CP_ASYNC16(dst, src) \
    asm volatile("cp.async.ca.shared.global [%0], [%1], 16;" :: "r"(dst), "l"(src) : "memory")
#define CP_COMMIT()  asm volatile("cp.async.commit_group;" ::: "memory")
#define CP_WAIT1()   asm volatile("cp.async.wait_group 1;" ::: "memory")
#define CP_WAIT0()   asm volatile("cp.async.wait_group 0;" ::: "memory")

// swizzled byte offset within a [rows][32]-half tile (64B rows, 4 x 16B chunks)
__device__ __forceinline__ uint32_t sw_off(int row, int kc) {
    return (uint32_t)(row * 64 + ((kc ^ ((row >> 1) & 3)) << 4));
}

// ---------------------------------------------------------------------------
// prep kernels
// ---------------------------------------------------------------------------
__global__ void bias_prep_kernel(const float* __restrict__ btab)
{
    const int h = blockIdx.x;
    const int t = threadIdx.x;
    #pragma unroll
    for (int i = 0; i < 16; i++) {
        int e  = t + i * 256;
        int qp = e >> 6, kp = e & 63;
        int dr = (qp >> 3) - (kp >> 3) + 7;
        int dc = (qp & 7)  - (kp & 7)  + 7;
        g_bias[h * 4096 + e] = __float2half(btab[(dr * 15 + dc) * HEADS + h]);
    }
}
__global__ void w_prep_kernel(const float* __restrict__ Wq,
                              const float* __restrict__ Wkv,
                              const float* __restrict__ Wp)
{
    const int idx = blockIdx.x * 256 + threadIdx.x;
    const int row = idx >> 8;
    const int k   = idx & 255;
    float v;
    if (row < 256)       v = Wq [(size_t)k * 256 + row];
    else if (row < 768)  v = Wkv[(size_t)k * 512 + (row - 256)];
    else                 v = Wp [(size_t)k * 256 + (row - 768)];
    g_wt[idx] = __float2half(v);
}

// ---------------------------------------------------------------------------
// fp16 GEMM (fp32 accum): C[M,N] = A[M,256] @ W[256,N] + bias[N]
// Block 128x128, BK=32, 8 warps (4x2), warp tile 32x64, mma.m16n8k16.
// W staged via 3-stage cp.async ring; A via cp.async (AHALF) or reg path.
// ---------------------------------------------------------------------------
template<bool GATHER, bool AHALF, bool CHALF>
__global__ __launch_bounds__(256, 2) void gemm_f16_kernel(
    const void* __restrict__ Av, const __half* __restrict__ Wt,
    const float* __restrict__ bias, void* __restrict__ Cv, int N)
{
    __shared__ __half Asm[3][128 * 32];
    __shared__ __half Wsm[3][128 * 32];

    const int t    = threadIdx.x;
    const int bm   = blockIdx.y, bn = blockIdx.x;
    const int lane = t & 31, warp = t >> 5;
    const int wm   = warp >> 1;
    const int wnn  = warp & 1;
    const int g    = lane >> 2;
    const int tq   = lane & 3;
    const int l15  = lane & 15, lhi = lane >> 4;

    // A mapping: row = t>>1, k16-block kb = t&1 (chunks 2kb, 2kb+1)
    const int arow = t >> 1, akb = t & 1;
    const int aSw  = (arow >> 1) & 3;
    size_t aoff;
    if (GATHER) {
        const int r    = bm * 128 + arow;
        const int wwin = r >> 6, p = r & 63;
        const int b    = wwin >> 8, widx = wwin & 255;
        const int wy   = widx >> 4, wx = widx & 15;
        const int py   = wy * 8 + (p >> 3);
        const int px   = wx * 8 + (p & 7);
        aoff = (((size_t)b * IMGH + py) * IMGW + px) * DIM;
    } else {
        aoff = (size_t)(bm * 128 + arow) * DIM;
    }
    const float*  ArowF = (const float*)Av + aoff;
    const __half* ArowH = (const __half*)Av + aoff;

    // W mapping: row wn_ = t>>1, k16-block wkb = t&1
    const int wn_ = t >> 1, wkb = t & 1;
    const int wSw = (wn_ >> 1) & 3;
    const __half* Wrow = Wt + (size_t)(bn * 128 + wn_) * DIM;

    const uint32_t aBase = (uint32_t)__cvta_generic_to_shared(Asm);
    const uint32_t wBase = (uint32_t)__cvta_generic_to_shared(Wsm);

    // ldsm lane addresses (within a slot)
    uint32_t aRow[2]; int aS[2];
    #pragma unroll
    for (int mi = 0; mi < 2; mi++) {
        int row = wm * 32 + mi * 16 + l15;
        aRow[mi] = aBase + row * 64;
        aS[mi]   = (row >> 1) & 3;
    }
    uint32_t bRow[4]; int bS[4];
    #pragma unroll
    for (int nt = 0; nt < 4; nt++) {
        int row = wnn * 64 + nt * 16 + l15;
        bRow[nt] = wBase + row * 64;
        bS[nt]   = (row >> 1) & 3;
    }

    float acc[2][8][4];
    #pragma unroll
    for (int mi = 0; mi < 2; mi++)
        #pragma unroll
        for (int ni = 0; ni < 8; ni++)
            #pragma unroll
            for (int j = 0; j < 4; j++) acc[mi][ni][j] = 0.f;

    uint32_t apk[8];   // fp32-A register path only

    // ---- staging helpers ----
    auto issueW = [&](int it) {
        const int slot = it % 3;
        const __half* src = Wrow + it * 32;
        #pragma unroll
        for (int j = 0; j < 2; j++) {
            const int c = 2 * wkb + j;
            CP_ASYNC16(wBase + (uint32_t)slot * 8192 + (uint32_t)wn_ * 64
                       + (uint32_t)(((c ^ wSw) << 4)), src + c * 8);
        }
    };
    auto issueA = [&](int it) {     // AHALF only
        const int slot = it % 3;
        const __half* src = ArowH + it * 32;
        #pragma unroll
        for (int j = 0; j < 2; j++) {
            const int c = 2 * akb + j;
            CP_ASYNC16(aBase + (uint32_t)slot * 8192 + (uint32_t)arow * 64
                       + (uint32_t)(((c ^ aSw) << 4)), src + c * 8);
        }
    };
    auto loadA = [&](int it) {      // fp32 A -> regs (pack to fp16)
        const float* ap = ArowF + it * 32 + akb * 16;
        #pragma unroll
        for (int j = 0; j < 4; j++) {
            float4 v = *(const float4*)(ap + j * 4);
            apk[2*j]   = pkh2(v.x, v.y);
            apk[2*j+1] = pkh2(v.z, v.w);
        }
    };
    auto storeA = [&](int slot) {   // regs -> smem slot (2 x STS.128)
        const uint32_t dst = aBase + (uint32_t)slot * 8192 + (uint32_t)arow * 64;
        const int c0 = 2 * akb, c1 = 2 * akb + 1;
        asm volatile("st.shared.v4.b32 [%0], {%1,%2,%3,%4};"
                     :: "r"(dst + (uint32_t)(((c0 ^ aSw) << 4))),
                        "r"(apk[0]), "r"(apk[1]), "r"(apk[2]), "r"(apk[3]) : "memory");
        asm volatile("st.shared.v4.b32 [%0], {%1,%2,%3,%4};"
                     :: "r"(dst + (uint32_t)(((c1 ^ aSw) << 4))),
                        "r"(apk[4]), "r"(apk[5]), "r"(apk[6]), "r"(apk[7]) : "memory");
    };

    // ---- prologue: stages 0,1 ----
    if (AHALF) { issueA(0); }
    issueW(0); CP_COMMIT();
    if (AHALF) { issueA(1); }
    issueW(1); CP_COMMIT();
    if (!AHALF) { loadA(0); storeA(0); }
    CP_WAIT1();          // stage 0 complete
    __syncthreads();

    for (int it = 0; it < 8; it++) {
        const uint32_t aOff = AHALF ? (uint32_t)(it % 3) * 8192
                                    : (uint32_t)(it & 1) * 8192;
        const uint32_t wOff = (uint32_t)(it % 3) * 8192;

        if (!AHALF && it < 7) loadA(it + 1);
        if (it < 6) {
            if (AHALF) issueA(it + 2);
            issueW(it + 2);
            CP_COMMIT();
        }

        // ---- compute 2 k16 blocks ----
        #pragma unroll
        for (int kb = 0; kb < 2; kb++) {
            const int kc = 2 * kb + lhi;
            uint32_t a[2][4];
            #pragma unroll
            for (int mi = 0; mi < 2; mi++)
                ldsm_x4(a[mi][0], a[mi][1], a[mi][2], a[mi][3],
                        aRow[mi] + aOff + (uint32_t)(((kc ^ aS[mi]) << 4)));
            uint32_t b[4][4];
            #pragma unroll
            for (int nt = 0; nt < 4; nt++)
                ldsm_x4(b[nt][0], b[nt][1], b[nt][2], b[nt][3],
                        bRow[nt] + wOff + (uint32_t)(((kc ^ bS[nt]) << 4)));
            #pragma unroll
            for (int mi = 0; mi < 2; mi++)
                #pragma unroll
                for (int nt = 0; nt < 4; nt++) {
                    mma_f16(acc[mi][2*nt],   a[mi][0], a[mi][1], a[mi][2], a[mi][3],
                            b[nt][0], b[nt][2]);
                    mma_f16(acc[mi][2*nt+1], a[mi][0], a[mi][1], a[mi][2], a[mi][3],
                            b[nt][1], b[nt][3]);
                }
        }

        if (!AHALF && it < 7) storeA((it + 1) & 1);
        if (it < 6)       { CP_WAIT1(); }
        else if (it == 6) { CP_WAIT0(); }
        __syncthreads();
    }

    // ---- epilogue ----
    #pragma unroll
    for (int mi = 0; mi < 2; mi++) {
        const int r0 = bm * 128 + wm * 32 + mi * 16 + g;
        #pragma unroll
        for (int ni = 0; ni < 8; ni++) {
            const int col = bn * 128 + wnn * 64 + ni * 8 + 2 * tq;
            float2 bv = *(const float2*)(bias + col);
            float c0 = acc[mi][ni][0] + bv.x, c1 = acc[mi][ni][1] + bv.y;
            float c2 = acc[mi][ni][2] + bv.x, c3 = acc[mi][ni][3] + bv.y;
            if (CHALF) {
                __half* C = (__half*)Cv;
                *(uint32_t*)(C + (size_t)r0 * N + col)       = pkh2(c0, c1);
                *(uint32_t*)(C + (size_t)(r0 + 8) * N + col) = pkh2(c2, c3);
            } else {
                float* C = (float*)Cv;
                *(float2*)(C + (size_t)r0 * N + col)       = make_float2(c0, c1);
                *(float2*)(C + (size_t)(r0 + 8) * N + col) = make_float2(c2, c3);
            }
        }
    }
}

// ---------------------------------------------------------------------------
// Attention (unchanged from R15): row-major padded staging + ldmatrix.
// ---------------------------------------------------------------------------
#define QSTR 40
__global__ __launch_bounds__(256) void attn_mma_kernel()
{
    __shared__ __half Qs[256 * QSTR];
    __shared__ __half Ks[64 * QSTR];
    __shared__ __half Vs[64 * QSTR];
    __shared__ __half Bs_h[64][66];

    const int blk = blockIdx.x;
    const int win = blk >> 3;
    const int h   = blk & 7;
    const int t   = threadIdx.x;
    const int lane = t & 31, warp = t >> 5;
    const int g   = lane >> 2;
    const int tq  = lane & 3;
    const int l15 = lane & 15, lhi = lane >> 4;
    const int l7  = lane & 7,  l8  = (lane >> 3) & 1;

    const uint32_t qBase = (uint32_t)__cvta_generic_to_shared(Qs);
    const uint32_t kBase = (uint32_t)__cvta_generic_to_shared(Ks);
    const uint32_t vBase = (uint32_t)__cvta_generic_to_shared(Vs);

    {
        const uint4* qp4 = (const uint4*)(g_q + ((size_t)(win * NQ + t)) * DIM + h * HD);
        const uint32_t dst = qBase + (uint32_t)t * 80;
        uint4 u0 = qp4[0], u1 = qp4[1], u2 = qp4[2], u3 = qp4[3];
        asm volatile("st.shared.v4.b32 [%0], {%1,%2,%3,%4};" :: "r"(dst),      "r"(u0.x),"r"(u0.y),"r"(u0.z),"r"(u0.w) : "memory");
        asm volatile("st.shared.v4.b32 [%0], {%1,%2,%3,%4};" :: "r"(dst + 16), "r"(u1.x),"r"(u1.y),"r"(u1.z),"r"(u1.w) : "memory");
        asm volatile("st.shared.v4.b32 [%0], {%1,%2,%3,%4};" :: "r"(dst + 32), "r"(u2.x),"r"(u2.y),"r"(u2.z),"r"(u2.w) : "memory");
        asm volatile("st.shared.v4.b32 [%0], {%1,%2,%3,%4};" :: "r"(dst + 48), "r"(u3.x),"r"(u3.y),"r"(u3.z),"r"(u3.w) : "memory");
    }
    if (t < 128) {
        const int key = t & 63;
        const size_t src = (size_t)(win * WS2 + key) * 512 + ((t < 64) ? 0 : (size_t)DIM) + h * HD;
        const uint4* p4 = (const uint4*)(g_kv + src);
        const uint32_t dst = ((t < 64) ? kBase : vBase) + (uint32_t)key * 80;
        uint4 u0 = p4[0], u1 = p4[1], u2 = p4[2], u3 = p4[3];
        asm volatile("st.shared.v4.b32 [%0], {%1,%2,%3,%4};" :: "r"(dst),      "r"(u0.x),"r"(u0.y),"r"(u0.z),"r"(u0.w) : "memory");
        asm volatile("st.shared.v4.b32 [%0], {%1,%2,%3,%4};" :: "r"(dst + 16), "r"(u1.x),"r"(u1.y),"r"(u1.z),"r"(u1.w) : "memory");
        asm volatile("st.shared.v4.b32 [%0], {%1,%2,%3,%4};" :: "r"(dst + 32), "r"(u2.x),"r"(u2.y),"r"(u2.z),"r"(u2.w) : "memory");
        asm volatile("st.shared.v4.b32 [%0], {%1,%2,%3,%4};" :: "r"(dst + 48), "r"(u3.x),"r"(u3.y),"r"(u3.z),"r"(u3.w) : "memory");
    }
    {
        const __half* gb = g_bias + h * 4096;
        #pragma unroll
        for (int i = 0; i < 2; i++) {
            int idx = t + i * 256;
            int qp = idx >> 3, c8 = (idx & 7) * 8;
            uint4 u = *(const uint4*)(gb + qp * 64 + c8);
            uint32_t* dst = (uint32_t*)((char*)&Bs_h[qp][0] + c8 * 2);
            dst[0] = u.x; dst[1] = u.y; dst[2] = u.z; dst[3] = u.w;
        }
    }
    __syncthreads();

    float acc[2][8][4];
    #pragma unroll
    for (int mi = 0; mi < 2; mi++)
        #pragma unroll
        for (int ni = 0; ni < 8; ni++)
            #pragma unroll
            for (int j = 0; j < 4; j++) acc[mi][ni][j] = 0.f;

    #pragma unroll
    for (int kb = 0; kb < 2; kb++) {
        const uint32_t cOff = (uint32_t)(2 * kb + lhi) * 16;
        uint32_t a[2][4];
        #pragma unroll
        for (int mi = 0; mi < 2; mi++)
            ldsm_x4(a[mi][0], a[mi][1], a[mi][2], a[mi][3],
                    qBase + (uint32_t)(warp * 32 + mi * 16 + l15) * 80 + cOff);
        uint32_t b[4][4];
        #pragma unroll
        for (int ng = 0; ng < 4; ng++)
            ldsm_x4(b[ng][0], b[ng][1], b[ng][2], b[ng][3],
                    kBase + (uint32_t)(ng * 16 + l15) * 80 + cOff);
        #pragma unroll
        for (int mi = 0; mi < 2; mi++)
            #pragma unroll
            for (int ng = 0; ng < 4; ng++) {
                mma_f16(acc[mi][2*ng],   a[mi][0], a[mi][1], a[mi][2], a[mi][3],
                        b[ng][0], b[ng][2]);
                mma_f16(acc[mi][2*ng+1], a[mi][0], a[mi][1], a[mi][2], a[mi][3],
                        b[ng][1], b[ng][3]);
            }
    }

    const float scale = 0.17677669529663687f;
    float inv_[2][2];
    #pragma unroll
    for (int mi = 0; mi < 2; mi++) {
        const int rA = warp * 32 + mi * 16 + g;
        const int qA = rA & 63, qB = (rA + 8) & 63;
        float mA = -1e30f, mB = -1e30f;
        #pragma unroll
        for (int ni = 0; ni < 8; ni++) {
            const int col = ni * 8 + 2 * tq;
            float2 bA = __half22float2(*(const __half2*)&Bs_h[qA][col]);
            float2 bB = __half22float2(*(const __half2*)&Bs_h[qB][col]);
            acc[mi][ni][0] = acc[mi][ni][0] * scale + bA.x;
            acc[mi][ni][1] = acc[mi][ni][1] * scale + bA.y;
            acc[mi][ni][2] = acc[mi][ni][2] * scale + bB.x;
            acc[mi][ni][3] = acc[mi][ni][3] * scale + bB.y;
            mA = fmaxf(mA, fmaxf(acc[mi][ni][0], acc[mi][ni][1]));
            mB = fmaxf(mB, fmaxf(acc[mi][ni][2], acc[mi][ni][3]));
        }
        mA = fmaxf(mA, __shfl_xor_sync(0xffffffff, mA, 1));
        mA = fmaxf(mA, __shfl_xor_sync(0xffffffff, mA, 2));
        mB = fmaxf(mB, __shfl_xor_sync(0xffffffff, mB, 1));
        mB = fmaxf(mB, __shfl_xor_sync(0xffffffff, mB, 2));
        float sA = 0.f, sB = 0.f;
        #pragma unroll
        for (int ni = 0; ni < 8; ni++) {
            float e0 = __expf(acc[mi][ni][0] - mA);
            float e1 = __expf(acc[mi][ni][1] - mA);
            float e2 = __expf(acc[mi][ni][2] - mB);
            float e3 = __expf(acc[mi][ni][3] - mB);
            acc[mi][ni][0] = e0; acc[mi][ni][1] = e1;
            acc[mi][ni][2] = e2; acc[mi][ni][3] = e3;
            sA += e0 + e1; sB += e2 + e3;
        }
        sA += __shfl_xor_sync(0xffffffff, sA, 1);
        sA += __shfl_xor_sync(0xffffffff, sA, 2);
        sB += __shfl_xor_sync(0xffffffff, sB, 1);
        sB += __shfl_xor_sync(0xffffffff, sB, 2);
        inv_[mi][0] = 1.f / sA;
        inv_[mi][1] = 1.f / sB;
    }

    float o[2][4][4];
    #pragma unroll
    for (int mi = 0; mi < 2; mi++)
        #pragma unroll
        for (int ni = 0; ni < 4; ni++)
            #pragma unroll
            for (int j = 0; j < 4; j++) o[mi][ni][j] = 0.f;

    #pragma unroll
    for (int kb = 0; kb < 4; kb++) {
        uint32_t a0[2], a1[2], a2[2], a3[2];
        #pragma unroll
        for (int mi = 0; mi < 2; mi++) {
            a0[mi] = pkh2(acc[mi][2*kb][0],     acc[mi][2*kb][1]);
            a1[mi] = pkh2(acc[mi][2*kb][2],     acc[mi][2*kb][3]);
            a2[mi] = pkh2(acc[mi][2*kb+1][0],   acc[mi][2*kb+1][1]);
            a3[mi] = pkh2(acc[mi][2*kb+1][2],   acc[mi][2*kb+1][3]);
        }
        const uint32_t vRow = vBase + (uint32_t)(kb * 16 + l8 * 8 + l7) * 80;
        #pragma unroll
        for (int ndp = 0; ndp < 2; ndp++) {
            uint32_t b0, b1, b2, b3;
            ldsm_x4_t(b0, b1, b2, b3, vRow + (uint32_t)(ndp * 2 + lhi) * 16);
            #pragma unroll
            for (int mi = 0; mi < 2; mi++) {
                mma_f16(o[mi][2*ndp],   a0[mi], a1[mi], a2[mi], a3[mi], b0, b1);
                mma_f16(o[mi][2*ndp+1], a0[mi], a1[mi], a2[mi], a3[mi], b2, b3);
            }
        }
    }

    #pragma unroll
    for (int mi = 0; mi < 2; mi++) {
        const int r = win * NQ + warp * 32 + mi * 16 + g;
        const float ivA = inv_[mi][0], ivB = inv_[mi][1];
        #pragma unroll
        for (int ni = 0; ni < 4; ni++) {
            const int col = h * HD + ni * 8 + 2 * tq;
            *(uint32_t*)(g_att + (size_t)r * DIM + col) =
                pkh2(o[mi][ni][0] * ivA, o[mi][ni][1] * ivA);
            *(uint32_t*)(g_att + (size_t)(r + 8) * DIM + col) =
                pkh2(o[mi][ni][2] * ivB, o[mi][ni][3] * ivB);
        }
    }
}

// ---------------------------------------------------------------------------
extern "C" void kernel_launch(void* const* d_in, const int* in_sizes, int n_in,
                              void* d_out, int out_size)
{
    const float* gauss = (const float*)d_in[0];
    const float* img   = (const float*)d_in[1];
    const float* btab  = (const float*)d_in[2];
    const float* Wq    = (const float*)d_in[3];
    const float* bq    = (const float*)d_in[4];
    const float* Wkv   = (const float*)d_in[5];
    const float* bkv   = (const float*)d_in[6];
    const float* Wp    = (const float*)d_in[7];
    const float* bp    = (const float*)d_in[8];
    float* out = (float*)d_out;

    void* pq = nullptr;   cudaGetSymbolAddress(&pq, g_q);
    void* pkv = nullptr;  cudaGetSymbolAddress(&pkv, g_kv);
    void* pa = nullptr;   cudaGetSymbolAddress(&pa, g_att);
    void* pwt = nullptr;  cudaGetSymbolAddress(&pwt, g_wt);
    const __half* wt = (const __half*)pwt;

    // 0) prep: bias table + transposed fp16 weights
    bias_prep_kernel<<<HEADS, 256>>>(btab);
    w_prep_kernel<<<1024, 256>>>(Wq, Wkv, Wp);
    // 1) Q projection: fp32 A -> fp16 C
    gemm_f16_kernel<false, false, true>
        <<<dim3(DIM / 128, ROWS_Q / 128), 256>>>(gauss, wt, bq, pq, DIM);
    // 2) KV projection (window gather): fp32 A -> fp16 C
    gemm_f16_kernel<true, false, true>
        <<<dim3((2 * DIM) / 128, ROWS_KV / 128), 256>>>(img, wt + 256 * DIM, bkv, pkv, 2 * DIM);
    // 3) Attention (ldmatrix staging, register-resident P)
    attn_mma_kernel<<<BW * HEADS, 256>>>();
    // 4) Output projection: fp16 A (cp.async) -> fp32 C (d_out)
    gemm_f16_kernel<false, true, false>
        <<<dim3(DIM / 128, ROWS_Q / 128), 256>>>(pa, wt + 768 * DIM, bp, out, DIM);
}